// round 16
// baseline (speedup 1.0000x reference)
#include <cuda_runtime.h>
#include <cuda_fp16.h>
#include <math.h>
#include <stdint.h>

#define B_ROWS 65536
#define T_DIM  365

// ---------------------------------------------------------------------------
// Scratch (device globals)
// ---------------------------------------------------------------------------
__device__ half g_x  [(size_t)B_ROWS * 384];
__device__ half g_h1 [(size_t)B_ROWS * 512];
__device__ half g_h2 [(size_t)B_ROWS * 256];
__device__ half g_st [(size_t)B_ROWS * 64];    // [stats(32) | zero(32)] per row
// weights transposed to [N, Kpad] fp16
__device__ half g_w1[512*384];
__device__ half g_w2[256*512];
__device__ half g_w3[128*256];
__device__ half g_w4[64*192];
__device__ half g_w5[32*64];
// per-row-block ready flags (zero-init; consumed+reset each run)
__device__ int g_flag[512];

// ---------------------------------------------------------------------------
// Baseline-PTX helpers (sm_80+; assemble on plain sm_103)
// ---------------------------------------------------------------------------
__device__ __forceinline__ uint32_t smem_u32(const void* p) {
    uint32_t a;
    asm("{ .reg .u64 t; cvta.to.shared.u64 t, %1; cvt.u32.u64 %0, t; }" : "=r"(a) : "l"(p));
    return a;
}
__device__ __forceinline__ void cpa16(uint32_t dst, const void* src) {
    asm volatile("cp.async.cg.shared.global [%0], [%1], 16;" :: "r"(dst), "l"(src));
}
#define CP_COMMIT() asm volatile("cp.async.commit_group;" ::: "memory")
template<int N>
__device__ __forceinline__ void cp_wait() {
    asm volatile("cp.async.wait_group %0;" :: "n"(N) : "memory");
}
#define LDM4(r, addr) \
    asm volatile("ldmatrix.sync.aligned.m8n8.x4.shared.b16 {%0,%1,%2,%3}, [%4];" \
        : "=r"((r)[0]), "=r"((r)[1]), "=r"((r)[2]), "=r"((r)[3]) : "r"(addr))
#define MMA_F16(d, a, b0, b1) \
    asm volatile("mma.sync.aligned.m16n8k16.row.col.f32.f16.f16.f32 " \
        "{%0,%1,%2,%3}, {%4,%5,%6,%7}, {%8,%9}, {%0,%1,%2,%3};" \
        : "+f"((d)[0]), "+f"((d)[1]), "+f"((d)[2]), "+f"((d)[3]) \
        : "r"((a)[0]), "r"((a)[1]), "r"((a)[2]), "r"((a)[3]), \
          "r"(b0), "r"(b1))

// ---------------------------------------------------------------------------
// GEMM tile body (proven 128x128 config): 8 warps 4m x 2n, 3-stage cp.async.
// ---------------------------------------------------------------------------
template<int NC>
__device__ __forceinline__ void gemm_body(
    const half* __restrict__ A, const half* __restrict__ W,
    const float* __restrict__ bias, half* __restrict__ Oh, int ldc,
    int m0, int n0, uint32_t sb, int tid, int wid, int lane)
{
    constexpr int KPAD  = NC * 64;
    constexpr int STAGE = 32768;

    const int wm = (wid >> 1) * 32;
    const int wn = (wid & 1) * 64;

    float acc[2][8][4];
    #pragma unroll
    for (int i = 0; i < 2; i++)
        #pragma unroll
        for (int j = 0; j < 8; j++)
            #pragma unroll
            for (int q = 0; q < 4; q++) acc[i][j][q] = 0.0f;

    auto stage = [&](int c) {
        const uint32_t sA = sb + (c % 3) * STAGE;
        const uint32_t sB = sA + 16384;
        #pragma unroll
        for (int i = tid; i < 1024; i += 256) {
            int r = i >> 3, cc = i & 7;
            cpa16(sA + r * 128 + ((cc ^ (r & 7)) << 4),
                  A + (size_t)(m0 + r) * KPAD + c * 64 + cc * 8);
        }
        #pragma unroll
        for (int i = tid; i < 1024; i += 256) {
            int r = i >> 3, cc = i & 7;
            cpa16(sB + r * 128 + ((cc ^ (r & 7)) << 4),
                  W + (size_t)(n0 + r) * KPAD + c * 64 + cc * 8);
        }
        CP_COMMIT();
    };

    stage(0);
    if (NC > 1) stage(1);

    for (int c = 0; c < NC; ++c) {
        if (c + 2 < NC)      { stage(c + 2); cp_wait<2>(); }
        else if (c + 1 < NC) { cp_wait<1>(); }
        else                 { cp_wait<0>(); }
        __syncthreads();

        const uint32_t sA = sb + (c % 3) * STAGE;
        const uint32_t sB = sA + 16384;

        #pragma unroll
        for (int ks = 0; ks < 4; ++ks) {
            const int g = ks * 2 + (lane >> 4);
            uint32_t a[2][4];
            #pragma unroll
            for (int mi = 0; mi < 2; ++mi) {
                int row = wm + mi * 16 + (lane & 15);
                LDM4(a[mi], sA + row * 128 + ((g ^ (row & 7)) << 4));
            }
            #pragma unroll
            for (int nb = 0; nb < 4; ++nb) {
                int row = wn + nb * 16 + (lane & 15);
                uint32_t t[4];
                LDM4(t, sB + row * 128 + ((g ^ (row & 7)) << 4));
                #pragma unroll
                for (int mi = 0; mi < 2; ++mi) {
                    MMA_F16(acc[mi][2*nb],   a[mi], t[0], t[2]);
                    MMA_F16(acc[mi][2*nb+1], a[mi], t[1], t[3]);
                }
            }
        }
        __syncthreads();
    }

    #pragma unroll
    for (int mi = 0; mi < 2; ++mi) {
        #pragma unroll
        for (int nf = 0; nf < 8; ++nf) {
            int r0 = m0 + wm + mi * 16 + (lane >> 2);
            int cb = n0 + wn + nf * 8 + (lane & 3) * 2;
            float bia0 = bias[cb], bia1 = bias[cb + 1];
            #pragma unroll
            for (int h = 0; h < 2; ++h) {
                int r = r0 + h * 8;
                float v0 = fmaxf(acc[mi][nf][h * 2]     + bia0, 0.0f);
                float v1 = fmaxf(acc[mi][nf][h * 2 + 1] + bia1, 0.0f);
                *(__half2*)(Oh + (size_t)r * ldc + cb) = __floats2half2_rn(v0, v1);
            }
        }
    }
}

// ---------------------------------------------------------------------------
// Standalone gemm1 kernel
// ---------------------------------------------------------------------------
template<int NC>
__global__ void __launch_bounds__(256, 2)
gemm_mma(const half* __restrict__ A, const half* __restrict__ W,
         const float* __restrict__ bias, half* __restrict__ Oh, int ldc)
{
    extern __shared__ __align__(1024) char sm[];
    gemm_body<NC>(A, W, bias, Oh, ldc,
                  blockIdx.y * 128, blockIdx.x * 128,
                  smem_u32(sm), threadIdx.x, threadIdx.x >> 5, threadIdx.x & 31);
}

// ---------------------------------------------------------------------------
// Tail body (round-12 proven, 96KB): L3 streamed, overlays, L4, L5, head.
// ---------------------------------------------------------------------------
__device__ __forceinline__ void tail_body(
    int m0, char* sm, uint32_t sb, int tid, int wid, int lane,
    const half* __restrict__ h2g, const half* __restrict__ W3,
    const half* __restrict__ stg, const half* __restrict__ W4,
    const half* __restrict__ W5,
    const float* __restrict__ b3,  const float* __restrict__ bc1,
    const float* __restrict__ bc2,
    const float* __restrict__ Wc3, const float* __restrict__ bc3,
    float* __restrict__ out)
{
    constexpr int SW4 = 0;
    constexpr int SW5 = 24576;
    constexpr int SST = 28672;
    constexpr int SC1 = 45056;
    constexpr int SH3 = 65536;
    constexpr int SC2 = 65536;

    float* c2s = (float*)(sm + SC2);
    const int wm = (wid >> 1) * 32;

    auto stage_hw = [&](int c) {
        const uint32_t sP = sb + (c & 1) * 16384;
        const uint32_t sQ = sb + 32768 + (c & 1) * 16384;
        #pragma unroll
        for (int i = tid; i < 1024; i += 256) {
            int r = i >> 3, g = i & 7;
            cpa16(sP + r * 128 + ((g ^ (r & 7)) << 4),
                  h2g + (size_t)(m0 + r) * 256 + c * 64 + g * 8);
        }
        #pragma unroll
        for (int i = tid; i < 1024; i += 256) {
            int r = i >> 3, g = i & 7;
            cpa16(sQ + r * 128 + ((g ^ (r & 7)) << 4),
                  W3 + (size_t)r * 256 + c * 64 + g * 8);
        }
        CP_COMMIT();
    };

    stage_hw(0);
    stage_hw(1);

    float acc3[2][8][4];
    #pragma unroll
    for (int i = 0; i < 2; i++)
        #pragma unroll
        for (int j = 0; j < 8; j++)
            #pragma unroll
            for (int q = 0; q < 4; q++) acc3[i][j][q] = 0.0f;

    const int wn3 = (wid & 1) * 64;
    #pragma unroll
    for (int c = 0; c < 4; ++c) {
        if (c < 3) cp_wait<1>(); else cp_wait<0>();
        __syncthreads();
        const uint32_t sA = sb + (c & 1) * 16384;
        const uint32_t sB = sb + 32768 + (c & 1) * 16384;
        #pragma unroll
        for (int ks = 0; ks < 4; ++ks) {
            const int g = ks * 2 + (lane >> 4);
            uint32_t a[2][4];
            #pragma unroll
            for (int mi = 0; mi < 2; ++mi) {
                int row = wm + mi * 16 + (lane & 15);
                LDM4(a[mi], sA + row * 128 + ((g ^ (row & 7)) << 4));
            }
            #pragma unroll
            for (int nb = 0; nb < 4; ++nb) {
                int row = wn3 + nb * 16 + (lane & 15);
                uint32_t t[4];
                LDM4(t, sB + row * 128 + ((g ^ (row & 7)) << 4));
                #pragma unroll
                for (int mi = 0; mi < 2; ++mi) {
                    MMA_F16(acc3[mi][2*nb],   a[mi], t[0], t[2]);
                    MMA_F16(acc3[mi][2*nb+1], a[mi], t[1], t[3]);
                }
            }
        }
        __syncthreads();
        if (c + 2 < 4) stage_hw(c + 2);
    }

    // overlay staging (W4/W5/stats) into dead stream buffers
    #pragma unroll
    for (int i = tid; i < 1536; i += 256) {
        int r = (i >> 3) & 63, c = i >> 9, g = i & 7;
        cpa16(sb + SW4 + c * 8192 + r * 128 + ((g ^ (r & 7)) << 4),
              W4 + (size_t)r * 192 + c * 64 + g * 8);
    }
    {
        int i = tid;
        if (i < 256) {
            int r = i >> 3, g = i & 7;
            cpa16(sb + SW5 + r * 128 + ((g ^ (r & 7)) << 4),
                  W5 + (size_t)r * 64 + g * 8);
        }
    }
    #pragma unroll
    for (int i = tid; i < 1024; i += 256) {
        int r = i >> 3, g = i & 7;
        cpa16(sb + SST + r * 128 + ((g ^ (r & 7)) << 4),
              stg + (size_t)(m0 + r) * 64 + g * 8);
    }
    CP_COMMIT();

    // h3 epilogue -> SH3
    #pragma unroll
    for (int mi = 0; mi < 2; ++mi) {
        #pragma unroll
        for (int nf = 0; nf < 8; ++nf) {
            int r0 = wm + mi * 16 + (lane >> 2);
            int cc = wn3 + nf * 8 + (lane & 3) * 2;
            float bia0 = b3[cc], bia1 = b3[cc + 1];
            int ch = cc >> 6, wc = cc & 63, g = wc >> 3, off = (wc & 7) * 2;
            #pragma unroll
            for (int h = 0; h < 2; ++h) {
                int r = r0 + h * 8;
                __half2 hv = __floats2half2_rn(
                    fmaxf(acc3[mi][nf][h * 2]     + bia0, 0.0f),
                    fmaxf(acc3[mi][nf][h * 2 + 1] + bia1, 0.0f));
                *(__half2*)(sm + SH3 + ch * 16384 + r * 128 + ((g ^ (r & 7)) << 4) + off) = hv;
            }
        }
    }
    cp_wait<0>();
    __syncthreads();

    // L4: c1[128x64] = relu([h3 | stats] @ W4^T + bc1)
    {
        const int wn = (wid & 1) * 32;
        float acc[2][4][4];
        #pragma unroll
        for (int i = 0; i < 2; i++)
            #pragma unroll
            for (int j = 0; j < 4; j++)
                #pragma unroll
                for (int q = 0; q < 4; q++) acc[i][j][q] = 0.0f;

        #pragma unroll
        for (int c = 0; c < 3; ++c) {
            const uint32_t aBase = (c < 2) ? (sb + SH3 + c * 16384) : (sb + SST);
            #pragma unroll
            for (int ks = 0; ks < 4; ++ks) {
                const int g = ks * 2 + (lane >> 4);
                uint32_t a[2][4];
                #pragma unroll
                for (int mi = 0; mi < 2; ++mi) {
                    int row = wm + mi * 16 + (lane & 15);
                    LDM4(a[mi], aBase + row * 128 + ((g ^ (row & 7)) << 4));
                }
                #pragma unroll
                for (int nb = 0; nb < 2; ++nb) {
                    int row = wn + nb * 16 + (lane & 15);
                    uint32_t t[4];
                    LDM4(t, sb + SW4 + c * 8192 + row * 128 + ((g ^ (row & 7)) << 4));
                    #pragma unroll
                    for (int mi = 0; mi < 2; ++mi) {
                        MMA_F16(acc[mi][2*nb],   a[mi], t[0], t[2]);
                        MMA_F16(acc[mi][2*nb+1], a[mi], t[1], t[3]);
                    }
                }
            }
        }
        #pragma unroll
        for (int mi = 0; mi < 2; ++mi) {
            #pragma unroll
            for (int nf = 0; nf < 4; ++nf) {
                int r0 = wm + mi * 16 + (lane >> 2);
                int cc = wn + nf * 8 + (lane & 3) * 2;
                float bia0 = bc1[cc], bia1 = bc1[cc + 1];
                int g = cc >> 3, off = (cc & 7) * 2;
                #pragma unroll
                for (int h = 0; h < 2; ++h) {
                    int r = r0 + h * 8;
                    __half2 hv = __floats2half2_rn(
                        fmaxf(acc[mi][nf][h * 2]     + bia0, 0.0f),
                        fmaxf(acc[mi][nf][h * 2 + 1] + bia1, 0.0f));
                    *(__half2*)(sm + SC1 + r * 128 + ((g ^ (r & 7)) << 4) + off) = hv;
                }
            }
        }
    }
    __syncthreads();

    // L5: c2[128x32] = relu(C1 @ W5^T + bc2)
    {
        const int wn = (wid & 1) * 16;
        float acc[2][2][4];
        #pragma unroll
        for (int i = 0; i < 2; i++)
            #pragma unroll
            for (int j = 0; j < 2; j++)
                #pragma unroll
                for (int q = 0; q < 4; q++) acc[i][j][q] = 0.0f;

        #pragma unroll
        for (int ks = 0; ks < 4; ++ks) {
            const int g = ks * 2 + (lane >> 4);
            uint32_t a[2][4];
            #pragma unroll
            for (int mi = 0; mi < 2; ++mi) {
                int row = wm + mi * 16 + (lane & 15);
                LDM4(a[mi], sb + SC1 + row * 128 + ((g ^ (row & 7)) << 4));
            }
            int row = wn + (lane & 15);
            uint32_t t[4];
            LDM4(t, sb + SW5 + row * 128 + ((g ^ (row & 7)) << 4));
            #pragma unroll
            for (int mi = 0; mi < 2; ++mi) {
                MMA_F16(acc[mi][0], a[mi], t[0], t[2]);
                MMA_F16(acc[mi][1], a[mi], t[1], t[3]);
            }
        }
        #pragma unroll
        for (int mi = 0; mi < 2; ++mi) {
            #pragma unroll
            for (int nf = 0; nf < 2; ++nf) {
                int r0 = wm + mi * 16 + (lane >> 2);
                int cc = wn + nf * 8 + (lane & 3) * 2;
                float bia0 = bc2[cc], bia1 = bc2[cc + 1];
                #pragma unroll
                for (int h = 0; h < 2; ++h) {
                    int r = r0 + h * 8;
                    c2s[r * 33 + cc]     = fmaxf(acc[mi][nf][h * 2]     + bia0, 0.0f);
                    c2s[r * 33 + cc + 1] = fmaxf(acc[mi][nf][h * 2 + 1] + bia1, 0.0f);
                }
            }
        }
    }
    __syncthreads();

    if (tid < 128) {
        float s = bc3[0];
        #pragma unroll
        for (int j = 0; j < 32; ++j) s = fmaf(c2s[tid * 33 + j], Wc3[j], s);
        out[m0 + tid] = 4.0f / (1.0f + expf(-s)) + 6.0f;
    }
}

// ---------------------------------------------------------------------------
// Fused gemm2 + tail: every CTA does its gemm2 tile; (m,1) signals & exits;
// (m,0) waits for its dispatch-adjacent sibling then runs the tail for row m.
// ---------------------------------------------------------------------------
__global__ void __launch_bounds__(256, 2)
gemm2_tail(const half* __restrict__ h1, const half* __restrict__ W2,
           const float* __restrict__ b2, half* __restrict__ h2,
           const half* __restrict__ W3, const half* __restrict__ stg,
           const half* __restrict__ W4, const half* __restrict__ W5,
           const float* __restrict__ b3,  const float* __restrict__ bc1,
           const float* __restrict__ bc2,
           const float* __restrict__ Wc3, const float* __restrict__ bc3,
           float* __restrict__ out)
{
    extern __shared__ __align__(1024) char sm[];
    const uint32_t sb = smem_u32(sm);
    const int tid  = threadIdx.x;
    const int wid  = tid >> 5;
    const int lane = tid & 31;
    const int m    = blockIdx.y;
    const int n    = blockIdx.x;

    // phase A: gemm2 tile (m, n)
    gemm_body<8>(h1, W2, b2, h2, 256, m * 128, n * 128, sb, tid, wid, lane);

    if (n == 1) {
        __syncthreads();
        if (tid == 0) { __threadfence(); atomicAdd(&g_flag[m], 1); }
        return;
    }

    // phase B (n == 0): wait for sibling, then tail for row-block m
    __syncthreads();
    if (tid == 0) {
        while (atomicAdd(&g_flag[m], 0) == 0) { __nanosleep(64); }
        g_flag[m] = 0;                 // reset for next graph replay
        __threadfence();
    }
    __syncthreads();

    tail_body(m * 128, sm, sb, tid, wid, lane,
              h2, W3, stg, W4, W5, b3, bc1, bc2, Wc3, bc3, out);
}

// ---------------------------------------------------------------------------
// Merged prep: CTAs [0,8192) = x->fp16 + stats + 6->32 projection;
//              CTAs [8192,9656) = all weight transposes/conversions.
// ---------------------------------------------------------------------------
__device__ __forceinline__ void conv_one(const float* W, int K, int N, int Kpad,
                                         half* o, int i) {
    int n = i / Kpad, kp = i % Kpad;
    o[i] = __float2half_rn((kp < K) ? W[(size_t)kp * N + n] : 0.0f);
}

__global__ void prep_all(const float* __restrict__ x,
                         const float* __restrict__ Ws,
                         const float* __restrict__ bs,
                         half* __restrict__ xh, half* __restrict__ st,
                         const float* __restrict__ W1, half* __restrict__ w1,
                         const float* __restrict__ W2, half* __restrict__ w2,
                         const float* __restrict__ W3, half* __restrict__ w3,
                         const float* __restrict__ Wc1, half* __restrict__ w4,
                         const float* __restrict__ Wc2, half* __restrict__ w5)
{
    if (blockIdx.x >= 8192) {
        int i = (blockIdx.x - 8192) * 256 + threadIdx.x;
        if      (i < 196608)  conv_one(W1, 365, 512, 384, w1, i);
        else if (i < 327680)  conv_one(W2, 512, 256, 512, w2, i - 196608);
        else if (i < 360448)  conv_one(W3, 256, 128, 256, w3, i - 327680);
        else if (i < 372736)  conv_one(Wc1, 160, 64, 192, w4, i - 360448);
        else if (i < 374784)  conv_one(Wc2, 64, 32, 64, w5, i - 372736);
        return;
    }

    int gwarp = (blockIdx.x * blockDim.x + threadIdx.x) >> 5;
    int lane  = threadIdx.x & 31;

    const float* row = x + (size_t)gwarp * T_DIM;
    constexpr int NV = 12;
    float v[NV];
    float sum = 0.0f, mn = INFINITY, mx = -INFINITY;
    #pragma unroll
    for (int i = 0; i < NV; i++) {
        int k = lane + 32 * i;
        float t = (k < T_DIM) ? row[k] : 0.0f;
        v[i] = t;
        if (k < T_DIM) { sum += t; mn = fminf(mn, t); mx = fmaxf(mx, t); }
    }
    half* xr = xh + (size_t)gwarp * 384;
    #pragma unroll
    for (int i = 0; i < NV; i++) xr[lane + 32 * i] = __float2half_rn(v[i]);

    #pragma unroll
    for (int off = 16; off; off >>= 1) {
        sum += __shfl_xor_sync(0xffffffffu, sum, off);
        mn   = fminf(mn, __shfl_xor_sync(0xffffffffu, mn, off));
        mx   = fmaxf(mx, __shfl_xor_sync(0xffffffffu, mx, off));
    }
    float mean = sum / (float)T_DIM;
    float s2 = 0.0f, s3 = 0.0f, s4 = 0.0f;
    #pragma unroll
    for (int i = 0; i < NV; i++) {
        int k = lane + 32 * i;
        if (k < T_DIM) {
            float c  = v[i] - mean;
            float c2 = c * c;
            s2 += c2; s3 += c2 * c; s4 += c2 * c2;
        }
    }
    #pragma unroll
    for (int off = 16; off; off >>= 1) {
        s2 += __shfl_xor_sync(0xffffffffu, s2, off);
        s3 += __shfl_xor_sync(0xffffffffu, s3, off);
        s4 += __shfl_xor_sync(0xffffffffu, s4, off);
    }
    float var  = s2 / (float)(T_DIM - 1);
    float sd   = sqrtf(var);
    float skew = (s3 / (float)T_DIM) / (sd * sd * sd + 1e-8f);
    float kurt = (s4 / (float)T_DIM) / (var * var + 1e-8f);

    float stv[6] = { mean, sd, mn, mx, skew, kurt };
    float o = bs[lane];
    #pragma unroll
    for (int i = 0; i < 6; i++) o = fmaf(stv[i], Ws[i * 32 + lane], o);

    size_t base = (size_t)gwarp * 64;
    st[base + lane]      = __float2half_rn(o);
    st[base + 32 + lane] = __float2half_rn(0.0f);
}

// ---------------------------------------------------------------------------
// Launch  (3 launches: prep, gemm1, fused gemm2+tail)
// ---------------------------------------------------------------------------
extern "C" void kernel_launch(void* const* d_in, const int* in_sizes, int n_in,
                              void* d_out, int out_size)
{
    const float* x   = (const float*)d_in[0];
    const float* W1  = (const float*)d_in[1];
    const float* b1  = (const float*)d_in[2];
    const float* W2  = (const float*)d_in[3];
    const float* b2  = (const float*)d_in[4];
    const float* W3  = (const float*)d_in[5];
    const float* b3  = (const float*)d_in[6];
    const float* Ws  = (const float*)d_in[7];
    const float* bs  = (const float*)d_in[8];
    const float* Wc1 = (const float*)d_in[9];
    const float* bc1 = (const float*)d_in[10];
    const float* Wc2 = (const float*)d_in[11];
    const float* bc2 = (const float*)d_in[12];
    const float* Wc3 = (const float*)d_in[13];
    const float* bc3 = (const float*)d_in[14];
    float* out = (float*)d_out;

    half *xh, *h1, *h2, *st, *w1, *w2, *w3, *w4, *w5;
    cudaGetSymbolAddress((void**)&xh, g_x);
    cudaGetSymbolAddress((void**)&h1, g_h1);
    cudaGetSymbolAddress((void**)&h2, g_h2);
    cudaGetSymbolAddress((void**)&st, g_st);
    cudaGetSymbolAddress((void**)&w1, g_w1);
    cudaGetSymbolAddress((void**)&w2, g_w2);
    cudaGetSymbolAddress((void**)&w3, g_w3);
    cudaGetSymbolAddress((void**)&w4, g_w4);
    cudaGetSymbolAddress((void**)&w5, g_w5);

    const int SMEM = 3 * 32768;                   // 98304 (both kernels)
    cudaFuncSetAttribute(gemm_mma<6>, cudaFuncAttributeMaxDynamicSharedMemorySize, SMEM);
    cudaFuncSetAttribute(gemm2_tail,  cudaFuncAttributeMaxDynamicSharedMemorySize, SMEM);

    // #0: merged prep (stats + x conversion + all weight conversions)
    prep_all<<<8192 + 1464, 256>>>(x, Ws, bs, xh, st,
                                   W1, w1, W2, w2, W3, w3, Wc1, w4, Wc2, w5);
    // #1: gemm1 [65536,384]x[384,512]
    gemm_mma<6><<<dim3(4, B_ROWS / 128), 256, SMEM>>>(xh, w1, b1, h1, 512);
    // #2: fused gemm2 + tail (row-block-local flag dependency)
    gemm2_tail<<<dim3(2, B_ROWS / 128), 256, SMEM>>>(
        h1, w2, b2, h2, w3, st, w4, w5, b3, bc1, bc2, Wc3, bc3, out);
}

// round 17
// speedup vs baseline: 1.0688x; 1.0688x over previous
#include <cuda_runtime.h>
#include <cuda_fp16.h>
#include <math.h>
#include <stdint.h>

#define B_ROWS 65536
#define T_DIM  365

// ---------------------------------------------------------------------------
// Scratch (device globals)
// ---------------------------------------------------------------------------
__device__ half g_x  [(size_t)B_ROWS * 384];
__device__ half g_h1 [(size_t)B_ROWS * 512];
__device__ half g_h2 [(size_t)B_ROWS * 256];
__device__ half g_st [(size_t)B_ROWS * 64];    // [stats(32) | zero(32)] per row
// weights transposed to [N, Kpad] fp16
__device__ half g_w1[512*384];
__device__ half g_w2[256*512];
__device__ half g_w3[128*256];
__device__ half g_w4[64*192];
__device__ half g_w5[32*64];

// ---------------------------------------------------------------------------
// Baseline-PTX helpers (sm_80+; assemble on plain sm_103)
// ---------------------------------------------------------------------------
__device__ __forceinline__ uint32_t smem_u32(const void* p) {
    uint32_t a;
    asm("{ .reg .u64 t; cvta.to.shared.u64 t, %1; cvt.u32.u64 %0, t; }" : "=r"(a) : "l"(p));
    return a;
}
__device__ __forceinline__ void cpa16(uint32_t dst, const void* src) {
    asm volatile("cp.async.cg.shared.global [%0], [%1], 16;" :: "r"(dst), "l"(src));
}
#define CP_COMMIT() asm volatile("cp.async.commit_group;" ::: "memory")
template<int N>
__device__ __forceinline__ void cp_wait() {
    asm volatile("cp.async.wait_group %0;" :: "n"(N) : "memory");
}
#define LDM4(r, addr) \
    asm volatile("ldmatrix.sync.aligned.m8n8.x4.shared.b16 {%0,%1,%2,%3}, [%4];" \
        : "=r"((r)[0]), "=r"((r)[1]), "=r"((r)[2]), "=r"((r)[3]) : "r"(addr))
#define MMA_F16(d, a, b0, b1) \
    asm volatile("mma.sync.aligned.m16n8k16.row.col.f32.f16.f16.f32 " \
        "{%0,%1,%2,%3}, {%4,%5,%6,%7}, {%8,%9}, {%0,%1,%2,%3};" \
        : "+f"((d)[0]), "+f"((d)[1]), "+f"((d)[2]), "+f"((d)[3]) \
        : "r"((a)[0]), "r"((a)[1]), "r"((a)[2]), "r"((a)[3]), \
          "r"(b0), "r"(b1))

// ---------------------------------------------------------------------------
// fp16 mma.sync GEMM (proven local optimum): CTA 128x128, 8 warps 4m x 2n
// (warp 32x64), 3-stage cp.async, 2 CTA/SM.  Used for gemm1/gemm2.
// ---------------------------------------------------------------------------
template<int NC>
__global__ void __launch_bounds__(256, 2)
gemm_mma(const half* __restrict__ A, const half* __restrict__ W,
         const float* __restrict__ bias, half* __restrict__ Oh, int ldc)
{
    constexpr int KPAD   = NC * 64;
    constexpr int STAGE  = 32768;            // A 16KB + B 16KB

    extern __shared__ __align__(1024) char sm[];
    const uint32_t sb = smem_u32(sm);

    const int tid  = threadIdx.x;
    const int wid  = tid >> 5;
    const int lane = tid & 31;
    const int m0   = blockIdx.y * 128;
    const int n0   = blockIdx.x * 128;
    const int wm   = (wid >> 1) * 32;
    const int wn   = (wid & 1) * 64;

    float acc[2][8][4];
    #pragma unroll
    for (int i = 0; i < 2; i++)
        #pragma unroll
        for (int j = 0; j < 8; j++)
            #pragma unroll
            for (int q = 0; q < 4; q++) acc[i][j][q] = 0.0f;

    auto stage = [&](int c) {
        const uint32_t sA = sb + (c % 3) * STAGE;
        const uint32_t sB = sA + 16384;
        #pragma unroll
        for (int i = tid; i < 1024; i += 256) {
            int r = i >> 3, cc = i & 7;
            cpa16(sA + r * 128 + ((cc ^ (r & 7)) << 4),
                  A + (size_t)(m0 + r) * KPAD + c * 64 + cc * 8);
        }
        #pragma unroll
        for (int i = tid; i < 1024; i += 256) {
            int r = i >> 3, cc = i & 7;
            cpa16(sB + r * 128 + ((cc ^ (r & 7)) << 4),
                  W + (size_t)(n0 + r) * KPAD + c * 64 + cc * 8);
        }
        CP_COMMIT();
    };

    stage(0);
    if (NC > 1) stage(1);

    for (int c = 0; c < NC; ++c) {
        if (c + 2 < NC)      { stage(c + 2); cp_wait<2>(); }
        else if (c + 1 < NC) { cp_wait<1>(); }
        else                 { cp_wait<0>(); }
        __syncthreads();

        const uint32_t sA = sb + (c % 3) * STAGE;
        const uint32_t sB = sA + 16384;

        #pragma unroll
        for (int ks = 0; ks < 4; ++ks) {
            const int g = ks * 2 + (lane >> 4);
            uint32_t a[2][4];
            #pragma unroll
            for (int mi = 0; mi < 2; ++mi) {
                int row = wm + mi * 16 + (lane & 15);
                LDM4(a[mi], sA + row * 128 + ((g ^ (row & 7)) << 4));
            }
            #pragma unroll
            for (int nb = 0; nb < 4; ++nb) {
                int row = wn + nb * 16 + (lane & 15);
                uint32_t t[4];
                LDM4(t, sB + row * 128 + ((g ^ (row & 7)) << 4));
                #pragma unroll
                for (int mi = 0; mi < 2; ++mi) {
                    MMA_F16(acc[mi][2*nb],   a[mi], t[0], t[2]);
                    MMA_F16(acc[mi][2*nb+1], a[mi], t[1], t[3]);
                }
            }
        }
        __syncthreads();
    }

    #pragma unroll
    for (int mi = 0; mi < 2; ++mi) {
        #pragma unroll
        for (int nf = 0; nf < 8; ++nf) {
            int r0 = m0 + wm + mi * 16 + (lane >> 2);
            int cb = n0 + wn + nf * 8 + (lane & 3) * 2;
            float bia0 = bias[cb], bia1 = bias[cb + 1];
            #pragma unroll
            for (int h = 0; h < 2; ++h) {
                int r = r0 + h * 8;
                float v0 = fmaxf(acc[mi][nf][h * 2]     + bia0, 0.0f);
                float v1 = fmaxf(acc[mi][nf][h * 2 + 1] + bia1, 0.0f);
                *(__half2*)(Oh + (size_t)r * ldc + cb) = __floats2half2_rn(v0, v1);
            }
        }
    }
}

// ---------------------------------------------------------------------------
// Fused tail v2 (96KB smem -> 2 CTA/SM):
//   L3: h3 = relu(h2@W3^T+b3), h2/W3 STREAMED in 16K double buffers
//   overlay after L3: W4/W5/stats/c1 into dead stream buffers
//   L4: c1 = relu([h3|st]@W4^T+bc1); L5: c2 = relu(c1@W5^T+bc2); head.
// smem: [0,64K)  stream: P0=0,P1=16K (h2), Q0=32K,Q1=48K (W3)
//       overlay: W4@0(24K), W5@24K(4K), st@28K(16K), c1@44K(16K)
//       [64K,96K) h3 (2 chunks); c2s overlays h3 chunk0 after L4
// ---------------------------------------------------------------------------
__global__ void __launch_bounds__(256, 2)
fused_tail(const half* __restrict__ h2g, const half* __restrict__ W3,
           const half* __restrict__ stg, const half* __restrict__ W4,
           const half* __restrict__ W5,
           const float* __restrict__ b3,  const float* __restrict__ bc1,
           const float* __restrict__ bc2,
           const float* __restrict__ Wc3, const float* __restrict__ bc3,
           float* __restrict__ out)
{
    constexpr int SW4 = 0;
    constexpr int SW5 = 24576;
    constexpr int SST = 28672;
    constexpr int SC1 = 45056;
    constexpr int SH3 = 65536;               // 32K
    constexpr int SC2 = 65536;               // float[128][33] overlays h3 after L4

    extern __shared__ __align__(1024) char sm[];
    const uint32_t sb = smem_u32(sm);
    float* c2s = (float*)(sm + SC2);

    const int tid  = threadIdx.x;
    const int wid  = tid >> 5;
    const int lane = tid & 31;
    const int m0   = blockIdx.x * 128;
    const int wm   = (wid >> 1) * 32;

    auto stage_hw = [&](int c) {
        const uint32_t sP = sb + (c & 1) * 16384;
        const uint32_t sQ = sb + 32768 + (c & 1) * 16384;
        #pragma unroll
        for (int i = tid; i < 1024; i += 256) {
            int r = i >> 3, g = i & 7;
            cpa16(sP + r * 128 + ((g ^ (r & 7)) << 4),
                  h2g + (size_t)(m0 + r) * 256 + c * 64 + g * 8);
        }
        #pragma unroll
        for (int i = tid; i < 1024; i += 256) {
            int r = i >> 3, g = i & 7;
            cpa16(sQ + r * 128 + ((g ^ (r & 7)) << 4),
                  W3 + (size_t)r * 256 + c * 64 + g * 8);
        }
        CP_COMMIT();
    };

    stage_hw(0);
    stage_hw(1);

    float acc3[2][8][4];
    #pragma unroll
    for (int i = 0; i < 2; i++)
        #pragma unroll
        for (int j = 0; j < 8; j++)
            #pragma unroll
            for (int q = 0; q < 4; q++) acc3[i][j][q] = 0.0f;

    const int wn3 = (wid & 1) * 64;
    #pragma unroll
    for (int c = 0; c < 4; ++c) {
        if (c < 3) cp_wait<1>(); else cp_wait<0>();
        __syncthreads();
        const uint32_t sA = sb + (c & 1) * 16384;
        const uint32_t sB = sb + 32768 + (c & 1) * 16384;
        #pragma unroll
        for (int ks = 0; ks < 4; ++ks) {
            const int g = ks * 2 + (lane >> 4);
            uint32_t a[2][4];
            #pragma unroll
            for (int mi = 0; mi < 2; ++mi) {
                int row = wm + mi * 16 + (lane & 15);
                LDM4(a[mi], sA + row * 128 + ((g ^ (row & 7)) << 4));
            }
            #pragma unroll
            for (int nb = 0; nb < 4; ++nb) {
                int row = wn3 + nb * 16 + (lane & 15);
                uint32_t t[4];
                LDM4(t, sB + row * 128 + ((g ^ (row & 7)) << 4));
                #pragma unroll
                for (int mi = 0; mi < 2; ++mi) {
                    MMA_F16(acc3[mi][2*nb],   a[mi], t[0], t[2]);
                    MMA_F16(acc3[mi][2*nb+1], a[mi], t[1], t[3]);
                }
            }
        }
        __syncthreads();
        if (c + 2 < 4) stage_hw(c + 2);
    }

    // overlay staging (W4/W5/stats) into dead stream buffers
    #pragma unroll
    for (int i = tid; i < 1536; i += 256) {
        int r = (i >> 3) & 63, c = i >> 9, g = i & 7;
        cpa16(sb + SW4 + c * 8192 + r * 128 + ((g ^ (r & 7)) << 4),
              W4 + (size_t)r * 192 + c * 64 + g * 8);
    }
    {
        int i = tid;
        if (i < 256) {
            int r = i >> 3, g = i & 7;
            cpa16(sb + SW5 + r * 128 + ((g ^ (r & 7)) << 4),
                  W5 + (size_t)r * 64 + g * 8);
        }
    }
    #pragma unroll
    for (int i = tid; i < 1024; i += 256) {
        int r = i >> 3, g = i & 7;
        cpa16(sb + SST + r * 128 + ((g ^ (r & 7)) << 4),
              stg + (size_t)(m0 + r) * 64 + g * 8);
    }
    CP_COMMIT();

    // h3 epilogue -> SH3
    #pragma unroll
    for (int mi = 0; mi < 2; ++mi) {
        #pragma unroll
        for (int nf = 0; nf < 8; ++nf) {
            int r0 = wm + mi * 16 + (lane >> 2);
            int cc = wn3 + nf * 8 + (lane & 3) * 2;
            float bia0 = b3[cc], bia1 = b3[cc + 1];
            int ch = cc >> 6, wc = cc & 63, g = wc >> 3, off = (wc & 7) * 2;
            #pragma unroll
            for (int h = 0; h < 2; ++h) {
                int r = r0 + h * 8;
                __half2 hv = __floats2half2_rn(
                    fmaxf(acc3[mi][nf][h * 2]     + bia0, 0.0f),
                    fmaxf(acc3[mi][nf][h * 2 + 1] + bia1, 0.0f));
                *(__half2*)(sm + SH3 + ch * 16384 + r * 128 + ((g ^ (r & 7)) << 4) + off) = hv;
            }
        }
    }
    cp_wait<0>();
    __syncthreads();

    // L4: c1[128x64] = relu([h3 | stats] @ W4^T + bc1), WN=32
    {
        const int wn = (wid & 1) * 32;
        float acc[2][4][4];
        #pragma unroll
        for (int i = 0; i < 2; i++)
            #pragma unroll
            for (int j = 0; j < 4; j++)
                #pragma unroll
                for (int q = 0; q < 4; q++) acc[i][j][q] = 0.0f;

        #pragma unroll
        for (int c = 0; c < 3; ++c) {
            const uint32_t aBase = (c < 2) ? (sb + SH3 + c * 16384) : (sb + SST);
            #pragma unroll
            for (int ks = 0; ks < 4; ++ks) {
                const int g = ks * 2 + (lane >> 4);
                uint32_t a[2][4];
                #pragma unroll
                for (int mi = 0; mi < 2; ++mi) {
                    int row = wm + mi * 16 + (lane & 15);
                    LDM4(a[mi], aBase + row * 128 + ((g ^ (row & 7)) << 4));
                }
                #pragma unroll
                for (int nb = 0; nb < 2; ++nb) {
                    int row = wn + nb * 16 + (lane & 15);
                    uint32_t t[4];
                    LDM4(t, sb + SW4 + c * 8192 + row * 128 + ((g ^ (row & 7)) << 4));
                    #pragma unroll
                    for (int mi = 0; mi < 2; ++mi) {
                        MMA_F16(acc[mi][2*nb],   a[mi], t[0], t[2]);
                        MMA_F16(acc[mi][2*nb+1], a[mi], t[1], t[3]);
                    }
                }
            }
        }
        #pragma unroll
        for (int mi = 0; mi < 2; ++mi) {
            #pragma unroll
            for (int nf = 0; nf < 4; ++nf) {
                int r0 = wm + mi * 16 + (lane >> 2);
                int cc = wn + nf * 8 + (lane & 3) * 2;
                float bia0 = bc1[cc], bia1 = bc1[cc + 1];
                int g = cc >> 3, off = (cc & 7) * 2;
                #pragma unroll
                for (int h = 0; h < 2; ++h) {
                    int r = r0 + h * 8;
                    __half2 hv = __floats2half2_rn(
                        fmaxf(acc[mi][nf][h * 2]     + bia0, 0.0f),
                        fmaxf(acc[mi][nf][h * 2 + 1] + bia1, 0.0f));
                    *(__half2*)(sm + SC1 + r * 128 + ((g ^ (r & 7)) << 4) + off) = hv;
                }
            }
        }
    }
    __syncthreads();

    // L5: c2[128x32] = relu(C1 @ W5^T + bc2), WN=16
    {
        const int wn = (wid & 1) * 16;
        float acc[2][2][4];
        #pragma unroll
        for (int i = 0; i < 2; i++)
            #pragma unroll
            for (int j = 0; j < 2; j++)
                #pragma unroll
                for (int q = 0; q < 4; q++) acc[i][j][q] = 0.0f;

        #pragma unroll
        for (int ks = 0; ks < 4; ++ks) {
            const int g = ks * 2 + (lane >> 4);
            uint32_t a[2][4];
            #pragma unroll
            for (int mi = 0; mi < 2; ++mi) {
                int row = wm + mi * 16 + (lane & 15);
                LDM4(a[mi], sb + SC1 + row * 128 + ((g ^ (row & 7)) << 4));
            }
            int row = wn + (lane & 15);
            uint32_t t[4];
            LDM4(t, sb + SW5 + row * 128 + ((g ^ (row & 7)) << 4));
            #pragma unroll
            for (int mi = 0; mi < 2; ++mi) {
                MMA_F16(acc[mi][0], a[mi], t[0], t[2]);
                MMA_F16(acc[mi][1], a[mi], t[1], t[3]);
            }
        }
        #pragma unroll
        for (int mi = 0; mi < 2; ++mi) {
            #pragma unroll
            for (int nf = 0; nf < 2; ++nf) {
                int r0 = wm + mi * 16 + (lane >> 2);
                int cc = wn + nf * 8 + (lane & 3) * 2;
                float bia0 = bc2[cc], bia1 = bc2[cc + 1];
                #pragma unroll
                for (int h = 0; h < 2; ++h) {
                    int r = r0 + h * 8;
                    c2s[r * 33 + cc]     = fmaxf(acc[mi][nf][h * 2]     + bia0, 0.0f);
                    c2s[r * 33 + cc + 1] = fmaxf(acc[mi][nf][h * 2 + 1] + bia1, 0.0f);
                }
            }
        }
    }
    __syncthreads();

    if (tid < 128) {
        float s = bc3[0];
        #pragma unroll
        for (int j = 0; j < 32; ++j) s = fmaf(c2s[tid * 33 + j], Wc3[j], s);
        out[m0 + tid] = 4.0f / (1.0f + expf(-s)) + 6.0f;
    }
}

// ---------------------------------------------------------------------------
// Merged prep: CTAs [0,8192) = x->fp16 + stats + 6->32 projection;
//              CTAs [8192,9656) = all weight transposes/conversions.
// ---------------------------------------------------------------------------
__device__ __forceinline__ void conv_one(const float* W, int K, int N, int Kpad,
                                         half* o, int i) {
    int n = i / Kpad, kp = i % Kpad;
    o[i] = __float2half_rn((kp < K) ? W[(size_t)kp * N + n] : 0.0f);
}

__global__ void prep_all(const float* __restrict__ x,
                         const float* __restrict__ Ws,
                         const float* __restrict__ bs,
                         half* __restrict__ xh, half* __restrict__ st,
                         const float* __restrict__ W1, half* __restrict__ w1,
                         const float* __restrict__ W2, half* __restrict__ w2,
                         const float* __restrict__ W3, half* __restrict__ w3,
                         const float* __restrict__ Wc1, half* __restrict__ w4,
                         const float* __restrict__ Wc2, half* __restrict__ w5)
{
    if (blockIdx.x >= 8192) {
        int i = (blockIdx.x - 8192) * 256 + threadIdx.x;
        if      (i < 196608)  conv_one(W1, 365, 512, 384, w1, i);
        else if (i < 327680)  conv_one(W2, 512, 256, 512, w2, i - 196608);
        else if (i < 360448)  conv_one(W3, 256, 128, 256, w3, i - 327680);
        else if (i < 372736)  conv_one(Wc1, 160, 64, 192, w4, i - 360448);
        else if (i < 374784)  conv_one(Wc2, 64, 32, 64, w5, i - 372736);
        return;
    }

    int gwarp = (blockIdx.x * blockDim.x + threadIdx.x) >> 5;
    int lane  = threadIdx.x & 31;

    const float* row = x + (size_t)gwarp * T_DIM;
    constexpr int NV = 12;
    float v[NV];
    float sum = 0.0f, mn = INFINITY, mx = -INFINITY;
    #pragma unroll
    for (int i = 0; i < NV; i++) {
        int k = lane + 32 * i;
        float t = (k < T_DIM) ? row[k] : 0.0f;
        v[i] = t;
        if (k < T_DIM) { sum += t; mn = fminf(mn, t); mx = fmaxf(mx, t); }
    }
    half* xr = xh + (size_t)gwarp * 384;
    #pragma unroll
    for (int i = 0; i < NV; i++) xr[lane + 32 * i] = __float2half_rn(v[i]);

    #pragma unroll
    for (int off = 16; off; off >>= 1) {
        sum += __shfl_xor_sync(0xffffffffu, sum, off);
        mn   = fminf(mn, __shfl_xor_sync(0xffffffffu, mn, off));
        mx   = fmaxf(mx, __shfl_xor_sync(0xffffffffu, mx, off));
    }
    float mean = sum / (float)T_DIM;
    float s2 = 0.0f, s3 = 0.0f, s4 = 0.0f;
    #pragma unroll
    for (int i = 0; i < NV; i++) {
        int k = lane + 32 * i;
        if (k < T_DIM) {
            float c  = v[i] - mean;
            float c2 = c * c;
            s2 += c2; s3 += c2 * c; s4 += c2 * c2;
        }
    }
    #pragma unroll
    for (int off = 16; off; off >>= 1) {
        s2 += __shfl_xor_sync(0xffffffffu, s2, off);
        s3 += __shfl_xor_sync(0xffffffffu, s3, off);
        s4 += __shfl_xor_sync(0xffffffffu, s4, off);
    }
    float var  = s2 / (float)(T_DIM - 1);
    float sd   = sqrtf(var);
    float skew = (s3 / (float)T_DIM) / (sd * sd * sd + 1e-8f);
    float kurt = (s4 / (float)T_DIM) / (var * var + 1e-8f);

    float stv[6] = { mean, sd, mn, mx, skew, kurt };
    float o = bs[lane];
    #pragma unroll
    for (int i = 0; i < 6; i++) o = fmaf(stv[i], Ws[i * 32 + lane], o);

    size_t base = (size_t)gwarp * 64;
    st[base + lane]      = __float2half_rn(o);
    st[base + 32 + lane] = __float2half_rn(0.0f);
}

// ---------------------------------------------------------------------------
// Launch  (4 launches; best measured configuration, 187.84 us)
// ---------------------------------------------------------------------------
extern "C" void kernel_launch(void* const* d_in, const int* in_sizes, int n_in,
                              void* d_out, int out_size)
{
    const float* x   = (const float*)d_in[0];
    const float* W1  = (const float*)d_in[1];
    const float* b1  = (const float*)d_in[2];
    const float* W2  = (const float*)d_in[3];
    const float* b2  = (const float*)d_in[4];
    const float* W3  = (const float*)d_in[5];
    const float* b3  = (const float*)d_in[6];
    const float* Ws  = (const float*)d_in[7];
    const float* bs  = (const float*)d_in[8];
    const float* Wc1 = (const float*)d_in[9];
    const float* bc1 = (const float*)d_in[10];
    const float* Wc2 = (const float*)d_in[11];
    const float* bc2 = (const float*)d_in[12];
    const float* Wc3 = (const float*)d_in[13];
    const float* bc3 = (const float*)d_in[14];
    float* out = (float*)d_out;

    half *xh, *h1, *h2, *st, *w1, *w2, *w3, *w4, *w5;
    cudaGetSymbolAddress((void**)&xh, g_x);
    cudaGetSymbolAddress((void**)&h1, g_h1);
    cudaGetSymbolAddress((void**)&h2, g_h2);
    cudaGetSymbolAddress((void**)&st, g_st);
    cudaGetSymbolAddress((void**)&w1, g_w1);
    cudaGetSymbolAddress((void**)&w2, g_w2);
    cudaGetSymbolAddress((void**)&w3, g_w3);
    cudaGetSymbolAddress((void**)&w4, g_w4);
    cudaGetSymbolAddress((void**)&w5, g_w5);

    const int SMGEMM = 3 * 32768;                 // 98304
    const int SMTAIL = 98304;                     // 64K stream + 32K h3 (overlays inside)
    cudaFuncSetAttribute(gemm_mma<6>, cudaFuncAttributeMaxDynamicSharedMemorySize, SMGEMM);
    cudaFuncSetAttribute(gemm_mma<8>, cudaFuncAttributeMaxDynamicSharedMemorySize, SMGEMM);
    cudaFuncSetAttribute(fused_tail,  cudaFuncAttributeMaxDynamicSharedMemorySize, SMTAIL);

    // #0: merged prep (stats + x conversion + all weight conversions)
    prep_all<<<8192 + 1464, 256>>>(x, Ws, bs, xh, st,
                                   W1, w1, W2, w2, W3, w3, Wc1, w4, Wc2, w5);
    // #1: gemm1 [65536,384]x[384,512]
    gemm_mma<6><<<dim3(4, B_ROWS / 128), 256, SMGEMM>>>(xh, w1, b1, h1, 512);
    // #2: gemm2 [65536,512]x[512,256]
    gemm_mma<8><<<dim3(2, B_ROWS / 128), 256, SMGEMM>>>(h1, w2, b2, h2, 256);
    // #3: fused layers 3+4+5+head, 2 CTA/SM
    fused_tail<<<B_ROWS / 128, 256, SMTAIL>>>(h2, w3, st, w4, w5,
                                              b3, bc1, bc2, Wc3, bc3, out);
}